// round 1
// baseline (speedup 1.0000x reference)
#include <cuda_runtime.h>

#define N_NODES   8192
#define B_BATCH   2
#define D_IN      64
#define D_OUT     32
#define K_ITERS   4
#define C_CH      (K_ITERS * D_OUT)   // 128
#define ALPHA_F   0.1f
#define OMA_F     0.9f                 // 1 - alpha
#define BN_EPS_F  1e-5f
#define MAX_NNZ   256
#define NSAMP     (B_BATCH * N_NODES)  // 16384

// ---------------- device scratch (no allocations allowed) ----------------
__device__ float g_h0 [B_BATCH * N_NODES * D_OUT];      // alpha * (x0 @ W0)
__device__ float g_hk0[B_BATCH * N_NODES * D_OUT];      // ping
__device__ float g_hk1[B_BATCH * N_NODES * D_OUT];      // pong
__device__ int   g_cols[(size_t)N_NODES * MAX_NNZ];
__device__ float g_vals[(size_t)N_NODES * MAX_NNZ];
__device__ int   g_cnt [N_NODES];
__device__ float g_y   [(size_t)B_BATCH * N_NODES * C_CH];   // pre-BN concat
__device__ float g_psum[128 * C_CH];
__device__ float g_psq [128 * C_CH];
__device__ float g_scale[C_CH];
__device__ float g_shift[C_CH];

// ---------------- 1) input projections: h = x@W (->hk0), h0 = alpha*(x0@W0) ----
__global__ void gemm_kernel(const float* __restrict__ x,
                            const float* __restrict__ x0,
                            const float* __restrict__ W,
                            const float* __restrict__ W0) {
    __shared__ float Ws [D_IN * D_OUT];
    __shared__ float W0s[D_IN * D_OUT];
    __shared__ float xs [8][D_IN];
    __shared__ float x0s[8][D_IN];

    const int t = threadIdx.x;
    const int rowBase = blockIdx.x * 8;          // over 16384 = B*N rows

    for (int i = t; i < D_IN * D_OUT; i += 256) { Ws[i] = W[i]; W0s[i] = W0[i]; }
    for (int i = t; i < 8 * D_IN; i += 256) {
        int r = rowBase + (i >> 6);
        int d = i & 63;
        xs [i >> 6][d] = x [(size_t)r * D_IN + d];
        x0s[i >> 6][d] = x0[(size_t)r * D_IN + d];
    }
    __syncthreads();

    const int rr = t >> 5;
    const int f  = t & 31;
    const int row = rowBase + rr;
    float acc = 0.f, acc0 = 0.f;
#pragma unroll
    for (int d = 0; d < D_IN; ++d) {
        acc  = fmaf(xs [rr][d], Ws [d * D_OUT + f], acc);
        acc0 = fmaf(x0s[rr][d], W0s[d * D_OUT + f], acc0);
    }
    g_hk0[(size_t)row * D_OUT + f] = acc;
    g_h0 [(size_t)row * D_OUT + f] = acc0 * ALPHA_F;
}

// ---------------- 2) dense -> padded CSR, values pre-scaled by (1-alpha) -----
__global__ void csr_kernel(const float* __restrict__ adj) {
    const int warp = (blockIdx.x * blockDim.x + threadIdx.x) >> 5;  // row id
    const int lane = threadIdx.x & 31;
    if (warp >= N_NODES) return;

    const float4* row = (const float4*)(adj + (size_t)warp * N_NODES);
    const int out = warp * MAX_NNZ;
    int base = 0;

    for (int ch = 0; ch < N_NODES / 128; ++ch) {
        float4 v = row[ch * 32 + lane];
        float e[4] = {v.x, v.y, v.z, v.w};
#pragma unroll
        for (int k = 0; k < 4; ++k) {
            const bool nz = (e[k] != 0.0f);
            const unsigned m = __ballot_sync(0xffffffffu, nz);
            if (nz) {
                int pos = base + __popc(m & ((1u << lane) - 1u));
                if (pos < MAX_NNZ) {
                    g_cols[out + pos] = ch * 128 + lane * 4 + k;
                    g_vals[out + pos] = e[k] * OMA_F;
                }
            }
            base += __popc(m);
        }
    }
    if (lane == 0) g_cnt[warp] = base < MAX_NNZ ? base : MAX_NNZ;
}

// ---------------- 3) SpMM iterate: dst = (1-a)*adj@src + a*h0; also write y ---
__global__ void spmm_kernel(const float* __restrict__ src,
                            float* __restrict__ dst, int kslice) {
    const int r    = (blockIdx.x * blockDim.x + threadIdx.x) >> 5;  // row
    const int lane = threadIdx.x & 31;                              // feature
    if (r >= N_NODES) return;

    const int   cnt  = g_cnt[r];
    const int*  cols = g_cols + r * MAX_NNZ;
    const float* vals = g_vals + r * MAX_NNZ;

    float acc0 = g_h0[(size_t)r * D_OUT + lane];
    float acc1 = g_h0[(size_t)(N_NODES + r) * D_OUT + lane];

    for (int b = 0; b < cnt; b += 32) {
        const int j = b + lane;
        int c = 0; float v = 0.f;
        if (j < cnt) { c = cols[j]; v = vals[j]; }
        const int m = (cnt - b) < 32 ? (cnt - b) : 32;
        for (int tt = 0; tt < m; ++tt) {
            const int   cc = __shfl_sync(0xffffffffu, c, tt);
            const float vv = __shfl_sync(0xffffffffu, v, tt);
            acc0 = fmaf(vv, src[(size_t)cc * D_OUT + lane], acc0);
            acc1 = fmaf(vv, src[(size_t)(N_NODES + cc) * D_OUT + lane], acc1);
        }
    }
    dst[(size_t)r * D_OUT + lane]             = acc0;
    dst[(size_t)(N_NODES + r) * D_OUT + lane] = acc1;
    g_y[(size_t)r * C_CH + kslice * D_OUT + lane]             = acc0;
    g_y[(size_t)(N_NODES + r) * C_CH + kslice * D_OUT + lane] = acc1;
}

// ---------------- 4) BN partial stats (deterministic, no atomics) ------------
__global__ void bn_stats_kernel() {
    __shared__ float sh [256];
    __shared__ float sh2[256];
    const int c   = threadIdx.x & 127;
    const int rep = threadIdx.x >> 7;     // 0..1
    const int sbase = blockIdx.x * 128;   // 128 samples per block, 128 blocks

    float s = 0.f, ss = 0.f;
    for (int i = rep; i < 128; i += 2) {
        float v = g_y[(size_t)(sbase + i) * C_CH + c];
        s += v;
        ss = fmaf(v, v, ss);
    }
    sh [threadIdx.x] = s;
    sh2[threadIdx.x] = ss;
    __syncthreads();
    if (rep == 0) {
        g_psum[blockIdx.x * C_CH + c] = sh [c] + sh [c + 128];
        g_psq [blockIdx.x * C_CH + c] = sh2[c] + sh2[c + 128];
    }
}

// ---------------- 5) finalize BN params ---------------------------------------
__global__ void bn_final_kernel(const float* __restrict__ gamma,
                                const float* __restrict__ beta) {
    const int c = threadIdx.x;   // 128 threads
    float s = 0.f, ss = 0.f;
    for (int b = 0; b < 128; ++b) {
        s  += g_psum[b * C_CH + c];
        ss += g_psq [b * C_CH + c];
    }
    const float inv = 1.0f / (float)NSAMP;
    const float mean = s * inv;
    const float var  = ss * inv - mean * mean;
    const float rstd = rsqrtf(var + BN_EPS_F);
    const float sc   = gamma[c] * rstd;
    g_scale[c] = sc;
    g_shift[c] = beta[c] - mean * sc;
}

// ---------------- 6) normalize + ReLU -----------------------------------------
__global__ void norm_kernel(float* __restrict__ out) {
    const int idx = blockIdx.x * blockDim.x + threadIdx.x;  // float4 index
    // total float4 = B*N*C/4 = 524288
    float4 v = ((const float4*)g_y)[idx];
    const int c0 = (idx & 31) * 4;
    v.x = fmaxf(0.f, fmaf(v.x, g_scale[c0 + 0], g_shift[c0 + 0]));
    v.y = fmaxf(0.f, fmaf(v.y, g_scale[c0 + 1], g_shift[c0 + 1]));
    v.z = fmaxf(0.f, fmaf(v.z, g_scale[c0 + 2], g_shift[c0 + 2]));
    v.w = fmaxf(0.f, fmaf(v.w, g_scale[c0 + 3], g_shift[c0 + 3]));
    ((float4*)out)[idx] = v;
}

// ---------------- launch ---------------------------------------------------------
extern "C" void kernel_launch(void* const* d_in, const int* in_sizes, int n_in,
                              void* d_out, int out_size) {
    const float* x     = (const float*)d_in[0];
    const float* x0    = (const float*)d_in[1];
    const float* adj   = (const float*)d_in[2];
    const float* W     = (const float*)d_in[3];
    const float* W0    = (const float*)d_in[4];
    const float* gamma = (const float*)d_in[5];
    const float* beta  = (const float*)d_in[6];
    float* out = (float*)d_out;

    // resolve device-global addresses (host side; graph-capture safe)
    float *hk0, *hk1;
    cudaGetSymbolAddress((void**)&hk0, g_hk0);
    cudaGetSymbolAddress((void**)&hk1, g_hk1);

    gemm_kernel<<<(B_BATCH * N_NODES) / 8, 256>>>(x, x0, W, W0);
    csr_kernel<<<N_NODES / 8, 256>>>(adj);

    // 4 propagation iterates (ping-pong)
    spmm_kernel<<<N_NODES / 8, 256>>>(hk0, hk1, 0);
    spmm_kernel<<<N_NODES / 8, 256>>>(hk1, hk0, 1);
    spmm_kernel<<<N_NODES / 8, 256>>>(hk0, hk1, 2);
    spmm_kernel<<<N_NODES / 8, 256>>>(hk1, hk0, 3);

    bn_stats_kernel<<<NSAMP / 128, 256>>>();
    bn_final_kernel<<<1, C_CH>>>(gamma, beta);
    norm_kernel<<<(B_BATCH * N_NODES * C_CH / 4) / 256, 256>>>(out);
}